// round 10
// baseline (speedup 1.0000x reference)
#include <cuda_runtime.h>
#include <cuda_fp16.h>
#include <cstdint>

#define B_    512
#define D_    512
#define C_    50000
#define KSUB  3
#define NW    150000
#define SCALEF 64.0f
#define EPSN  1e-12f

// ---- GEMM tiling (R6 config, persistent) ----
#define BMg 128
#define BNg 96                   // 32 classes per tile
#define BKg 64                   // 64 fp16 = 128B rows in SMEM
#define NKC (D_/BKg)             // 8 chunks per tile
#define NRING 4
#define NTILE_N 1564             // ceil(150000/96)
#define NWP (NTILE_N*BNg)        // 150144 padded rows (zeros beyond NW)
#define NWARP 4
#define NTILES (4*NTILE_N)       // 6256
#define GRIDP 296                // 2 CTAs x 148 SMs, persistent
#define NBLK8 (NW/8)             // 18750 wprep blocks

#define A_STG 16384              // 128 rows x 128B
#define B_STG 12288              // 96 rows x 128B
#define STG   (A_STG + B_STG)    // 28672
#define DYN_SMEM (NRING*STG)     // 114688 -> 2 CTAs/SM

// ---- static device scratch ----
__device__ float g_xn[B_*D_];                 // normalized x fp32 (fixup)
__device__ float g_winv[NW];                  // 1/||w|| (fixup)
__device__ __half g_xph[NKC*B_*64];           // packed swizzled x_hi [c][m][64]
__device__ __half g_wph[(size_t)NKC*NWP*64];  // packed swizzled w_hi [c][n][64]
__device__ int   g_scnt[NTILE_N];             // per-stripe wprep progress

// ============================ helpers ============================
__device__ __forceinline__ uint32_t smem_u32(const void* p) {
    uint32_t a;
    asm("{ .reg .u64 t; cvta.to.shared.u64 t, %1; cvt.u32.u64 %0, t; }" : "=r"(a) : "l"(p));
    return a;
}
__device__ __forceinline__ int ld_acq(const int* p) {
    int v;
    asm volatile("ld.acquire.gpu.b32 %0, [%1];" : "=r"(v) : "l"(p) : "memory");
    return v;
}
__device__ __forceinline__ void ldsm_x4(uint32_t& r0, uint32_t& r1, uint32_t& r2,
                                        uint32_t& r3, uint32_t addr) {
    asm volatile("ldmatrix.sync.aligned.m8n8.x4.shared.b16 {%0,%1,%2,%3}, [%4];"
        : "=r"(r0), "=r"(r1), "=r"(r2), "=r"(r3) : "r"(addr));
}
__device__ __forceinline__ void mma16816(float* c, const uint32_t* a, const uint32_t* b) {
    asm volatile(
        "mma.sync.aligned.m16n8k16.row.col.f32.f16.f16.f32 "
        "{%0,%1,%2,%3}, {%4,%5,%6,%7}, {%8,%9}, {%0,%1,%2,%3};"
        : "+f"(c[0]), "+f"(c[1]), "+f"(c[2]), "+f"(c[3])
        : "r"(a[0]), "r"(a[1]), "r"(a[2]), "r"(a[3]), "r"(b[0]), "r"(b[1]));
}
__device__ __forceinline__ void bulk_g2s(uint32_t dst, const void* src,
                                         uint32_t bytes, uint32_t mbar) {
    asm volatile(
        "cp.async.bulk.shared::cta.global.mbarrier::complete_tx::bytes [%0], [%1], %2, [%3];"
        :: "r"(dst), "l"(src), "r"(bytes), "r"(mbar) : "memory");
}
#define MBAR_INIT(a, n) asm volatile("mbarrier.init.shared.b64 [%0], %1;" :: "r"(a), "r"(n) : "memory")
#define MBAR_ARRIVE(a)  asm volatile("mbarrier.arrive.shared.b64 _, [%0];" :: "r"(a) : "memory")
#define MBAR_EXPECT_TX(a, n) asm volatile("mbarrier.arrive.expect_tx.shared.b64 _, [%0], %1;" :: "r"(a), "r"(n) : "memory")
#define MBAR_WAIT(a, par) do {                                                     \
    asm volatile(                                                                  \
        "{\n\t.reg .pred P1;\n\t"                                                  \
        "WL_%=:\n\t"                                                               \
        "mbarrier.try_wait.parity.acquire.cta.shared::cta.b64 P1, [%0], %1, 0x989680;\n\t" \
        "@P1 bra.uni WD_%=;\n\t"                                                   \
        "bra.uni WL_%=;\n\t"                                                       \
        "WD_%=:\n\t}"                                                              \
        :: "r"(a), "r"(par) : "memory");                                           \
} while (0)

// packed element offset: chunk c, global row, within-chunk 16B sub ci, sub-off
__device__ __forceinline__ size_t pack_off(int c, size_t rowStride, int row, int ci, int off) {
    return ((size_t)c * rowStride + row) * 64 + (size_t)((ci ^ (row & 7)) << 3) + off;
}

// ============================ Kernel Z: zero progress counters ============================
__global__ void zero_kernel() {
    int i = blockIdx.x * 256 + threadIdx.x;
    if (i < NTILE_N) g_scnt[i] = 0;
}

// ============================ Kernel 0: x prep ============================
__global__ void xprep_kernel(const float* __restrict__ x) {
    __shared__ float red[4];
    const int m = blockIdx.x;
    const int tid = threadIdx.x;            // 0..127, covers k = 4*tid
    float4 v = reinterpret_cast<const float4*>(x + m * D_)[tid];
    float ss = v.x * v.x + v.y * v.y + v.z * v.z + v.w * v.w;
    #pragma unroll
    for (int o = 16; o > 0; o >>= 1) ss += __shfl_xor_sync(0xffffffffu, ss, o);
    if ((tid & 31) == 0) red[tid >> 5] = ss;
    __syncthreads();
    float inv = 1.0f / fmaxf(sqrtf(red[0] + red[1] + red[2] + red[3]), EPSN);
    float u[4] = {v.x * inv, v.y * inv, v.z * inv, v.w * inv};
    reinterpret_cast<float4*>(g_xn)[m * (D_ / 4) + tid] =
        make_float4(u[0], u[1], u[2], u[3]);
    __half h[4];
    #pragma unroll
    for (int i = 0; i < 4; i++) h[i] = __float2half_rn(u[i]);
    int c  = tid >> 4;
    int ci = (tid & 15) >> 1;
    int of = 4 * (tid & 1);
    size_t e = pack_off(c, B_, m, ci, of);
    *reinterpret_cast<uint2*>(g_xph + e) = *reinterpret_cast<uint2*>(h);
}

// ============================ Kernel 1: w prep (descending, publishes progress) ============
__global__ void wprep_kernel(const float* __restrict__ w) {
    const int lane = threadIdx.x & 31;
    const int warp = threadIdx.x >> 5;
    const int rb   = NBLK8 - 1 - (int)blockIdx.x;   // descending row-blocks
    const int n    = rb * 8 + warp;
    const float4* wr = reinterpret_cast<const float4*>(w + (size_t)n * D_);
    float4 v[4];
    float ss = 0.0f;
    #pragma unroll
    for (int i = 0; i < 4; i++) {
        v[i] = wr[lane + i * 32];
        ss += v[i].x * v[i].x + v[i].y * v[i].y + v[i].z * v[i].z + v[i].w * v[i].w;
    }
    #pragma unroll
    for (int o = 16; o > 0; o >>= 1) ss += __shfl_xor_sync(0xffffffffu, ss, o);
    float inv = 1.0f / fmaxf(sqrtf(ss), EPSN);
    if (lane == 0) g_winv[n] = inv;
    #pragma unroll
    for (int i = 0; i < 4; i++) {
        __half h[4];
        h[0] = __float2half_rn(v[i].x * inv);
        h[1] = __float2half_rn(v[i].y * inv);
        h[2] = __float2half_rn(v[i].z * inv);
        h[3] = __float2half_rn(v[i].w * inv);
        int c  = (lane >> 4) + 2 * i;         // k = 4*lane + 128*i
        int ci = (lane & 15) >> 1;
        int of = 4 * (lane & 1);
        *reinterpret_cast<uint2*>(g_wph + pack_off(c, NWP, n, ci, of)) =
            *reinterpret_cast<uint2*>(h);
    }
    __threadfence();
    __syncthreads();
    if (threadIdx.x == 0) atomicAdd(&g_scnt[rb / 12], 1);   // 12 blocks per stripe
}

// ============================ Kernel 2: persistent HMMA GEMM + max-3 ============================
__global__ __launch_bounds__(128)
void gemm_hmma_kernel(float* __restrict__ out) {
    extern __shared__ __align__(1024) char dyn[];
    __shared__ __align__(8) uint64_t sFull[NRING], sEmpty[NRING];

    const uint32_t sb  = smem_u32(dyn);
    const int tid  = threadIdx.x;
    const int lane = tid & 31;
    const int wid  = tid >> 5;              // 0..3
    const int wm   = wid >> 1;              // 0..1 (64 rows each)
    const int wn   = wid & 1;               // 0..1 (48 cols each)

    const int myTiles = (NTILES - (int)blockIdx.x + GRIDP - 1) / GRIDP;
    const int gEnd = myTiles * NKC;         // total stages for this CTA

    if (tid == 0) {
        #pragma unroll
        for (int i = 0; i < NRING; i++) {
            MBAR_INIT(smem_u32(&sFull[i]), 1);
            MBAR_INIT(smem_u32(&sEmpty[i]), NWARP);
        }
    }
    __syncthreads();

    // producer: issue global stage g (tile g/8, chunk g%8)
    auto produce = [&](int g) {
        if (g >= gEnd) return;
        int slot = g & (NRING - 1);
        if (g >= NRING) MBAR_WAIT(smem_u32(&sEmpty[slot]), 1 ^ ((g >> 2) & 1));
        int tile = (int)blockIdx.x + (g >> 3) * GRIDP;
        int c    = g & 7;
        int pm   = (tile & 3) * BMg;
        int nbi  = NTILE_N - 1 - (tile >> 2);
        int pn   = nbi * BNg;
        // wait until wprep has published this stripe (release/acquire)
        int expc = NW - nbi * 96;
        if (expc > 96) expc = 96;
        if (expc > 0) {
            expc >>= 3;
            while (ld_acq(&g_scnt[nbi]) < expc) {}
        }
        uint32_t fb = smem_u32(&sFull[slot]);
        MBAR_EXPECT_TX(fb, STG);
        const __half* aSrc = g_xph + ((size_t)c * B_ + pm) * 64;
        const __half* bSrc = g_wph + ((size_t)c * NWP + pn) * 64;
        uint32_t base = sb + slot * STG;
        bulk_g2s(base, aSrc, A_STG, fb);
        bulk_g2s(base + A_STG, bSrc, B_STG, fb);
    };

    if (tid == 0) { produce(0); produce(1); produce(2); }

    for (int lt = 0; lt < myTiles; lt++) {
        const int tile = (int)blockIdx.x + lt * GRIDP;
        const int mblk = (tile & 3) * BMg;
        const int nb   = NTILE_N - 1 - (tile >> 2);

        float acc[4][6][4];
        #pragma unroll
        for (int i = 0; i < 4; i++)
            #pragma unroll
            for (int j = 0; j < 6; j++)
                #pragma unroll
                for (int q = 0; q < 4; q++) acc[i][j][q] = 0.0f;

        #pragma unroll 1
        for (int c = 0; c < NKC; c++) {
            const int g = lt * NKC + c;
            const int slot = g & (NRING - 1);
            MBAR_WAIT(smem_u32(&sFull[slot]), (g >> 2) & 1);
            uint32_t aBase = sb + slot * STG;
            uint32_t bBase = aBase + A_STG;

            #pragma unroll
            for (int kk = 0; kk < 4; kk++) {            // 4 k16 steps in BK=64
                const int ciA = 2 * kk + (lane >> 4);
                uint32_t a[4][4];
                #pragma unroll
                for (int mt = 0; mt < 4; mt++) {
                    int rr = wm * 64 + mt * 16 + (lane & 15);
                    uint32_t ad = aBase + rr * 128 + (((ciA ^ (rr & 7))) << 4);
                    ldsm_x4(a[mt][0], a[mt][1], a[mt][2], a[mt][3], ad);
                }
                uint32_t b[6][2];
                #pragma unroll
                for (int p = 0; p < 3; p++) {
                    int rr = wn * 48 + p * 16 + (lane & 15);
                    uint32_t ad = bBase + rr * 128 + (((ciA ^ (rr & 7))) << 4);
                    uint32_t r0, r1, r2, r3;
                    ldsm_x4(r0, r1, r2, r3, ad);
                    b[2 * p][0] = r0; b[2 * p][1] = r2;
                    b[2 * p + 1][0] = r1; b[2 * p + 1][1] = r3;
                }
                #pragma unroll
                for (int mt = 0; mt < 4; mt++)
                    #pragma unroll
                    for (int nt = 0; nt < 6; nt++)
                        mma16816(acc[mt][nt], a[mt], b[nt]);
            }
            if (c < NKC - 1) {                          // stage 7's arrive deferred
                if (lane == 0) MBAR_ARRIVE(smem_u32(&sEmpty[slot]));
                if (tid == 0) produce(g + 3);
            }
        }

        // ---- epilogue: stage into slot 3's smem (its empty not yet posted) ----
        float* st = reinterpret_cast<float*>(dyn + 3 * STG);   // [128][50]
        const int STR = 50;                 // even: float2 stores stay 8B-aligned
        const int clsBase = nb * (BNg / KSUB);                 // 32 classes/tile
        #pragma unroll
        for (int h = 0; h < 2; h++) {
            __syncthreads();                                   // prior readers done
            if (wn == h) {
                #pragma unroll
                for (int mt = 0; mt < 4; mt++) {
                    int r0 = wm * 64 + mt * 16 + (lane >> 2);
                    #pragma unroll
                    for (int nt = 0; nt < 6; nt++) {
                        int cc = nt * 8 + 2 * (lane & 3);
                        *reinterpret_cast<float2*>(&st[r0 * STR + cc]) =
                            make_float2(acc[mt][nt][0], acc[mt][nt][1]);
                        *reinterpret_cast<float2*>(&st[(r0 + 8) * STR + cc]) =
                            make_float2(acc[mt][nt][2], acc[mt][nt][3]);
                    }
                }
            }
            __syncthreads();
            for (int t = tid; t < BMg * 16; t += 128) {
                int r = t >> 4, cc = t & 15;
                int cls = clsBase + h * 16 + cc;
                if (cls < C_) {
                    const float* p = &st[r * STR + 3 * cc];
                    float v = fmaxf(p[0], fmaxf(p[1], p[2]));
                    out[(size_t)(mblk + r) * C_ + cls] = SCALEF * v;
                }
            }
        }
        __syncthreads();                                       // staging reads done
        {   // release slot 3 and let producer refill it
            const int g7 = lt * NKC + (NKC - 1);
            if (lane == 0) MBAR_ARRIVE(smem_u32(&sEmpty[g7 & (NRING - 1)]));
            if (tid == 0) produce(g7 + 3);
        }
    }
}

// ============================ Kernel 3: label fix-up ============================
__global__ void fixup_kernel(const int* __restrict__ label,
                             const float* __restrict__ w,
                             const float* __restrict__ margins,
                             float* __restrict__ out) {
    __shared__ float sdot[KSUB];
    const int b = blockIdx.x;
    const int lane = threadIdx.x & 31;
    const int warp = threadIdx.x >> 5;
    int l = label[b];
    if (l < 0) l = 0;
    if (l >= C_) l = C_ - 1;
    const int row = l * KSUB + warp;
    const float4* xr = reinterpret_cast<const float4*>(g_xn + (size_t)b * D_);
    const float4* wr = reinterpret_cast<const float4*>(w + (size_t)row * D_);
    float dot = 0.0f;
    #pragma unroll
    for (int i = 0; i < 4; i++) {
        float4 xa = xr[lane + i * 32];
        float4 wa = wr[lane + i * 32];
        dot += xa.x * wa.x + xa.y * wa.y + xa.z * wa.z + xa.w * wa.w;
    }
    #pragma unroll
    for (int o = 16; o > 0; o >>= 1) dot += __shfl_xor_sync(0xffffffffu, dot, o);
    if (lane == 0) sdot[warp] = dot * g_winv[row];
    __syncthreads();
    if (threadIdx.x == 0) {
        float c0 = sdot[0], c1 = sdot[1], c2 = sdot[2];
        float target = fmaxf(c0, fmaxf(c1, c2));
        float shift = 0.5f * (fabsf(c0 - c1) + fabsf(c0 - c2));
        float mg = margins[l];
        out[(size_t)b * C_ + l] = SCALEF * (target - mg * (1.0f + shift));
    }
}

// ============================ launch ============================
extern "C" void kernel_launch(void* const* d_in, const int* in_sizes, int n_in,
                              void* d_out, int out_size) {
    const float* input   = (const float*)d_in[0];      // (512, 512)
    const int*   label   = (const int*)d_in[1];        // (512,) int32
    const float* weights = (const float*)d_in[2];      // (150000, 512)
    const float* margins = (const float*)d_in[3];      // (50000,)
    float* out = (float*)d_out;                        // (512, 50000)

    static cudaStream_t s1 = nullptr;
    static cudaEvent_t  e0 = nullptr, e1 = nullptr;
    if (!s1) {   // first call is the (uncaptured) correctness run
        cudaStreamCreateWithFlags(&s1, cudaStreamNonBlocking);
        cudaEventCreateWithFlags(&e0, cudaEventDisableTiming);
        cudaEventCreateWithFlags(&e1, cudaEventDisableTiming);
        cudaFuncSetAttribute(gemm_hmma_kernel,
                             cudaFuncAttributeMaxDynamicSharedMemorySize, DYN_SMEM);
        cudaFuncSetAttribute(gemm_hmma_kernel,
                             cudaFuncAttributePreferredSharedMemoryCarveout, 100);
    }

    zero_kernel<<<(NTILE_N + 255) / 256, 256>>>();
    cudaEventRecord(e0, 0);

    // fork: wprep concurrent with GEMM; GEMM self-synchronizes per stripe
    cudaStreamWaitEvent(s1, e0, 0);
    wprep_kernel<<<NBLK8, 256, 0, s1>>>(weights);
    cudaEventRecord(e1, s1);

    xprep_kernel<<<B_, 128>>>(input);
    gemm_hmma_kernel<<<GRIDP, 128, DYN_SMEM>>>(out);

    // join: fixup needs g_winv (wprep) and GEMM's output in place
    cudaStreamWaitEvent(0, e1, 0);
    fixup_kernel<<<B_, 96>>>(label, weights, margins, out);
}

// round 11
// speedup vs baseline: 1.1198x; 1.1198x over previous
#include <cuda_runtime.h>
#include <cuda_fp16.h>
#include <cstdint>

#define B_    512
#define D_    512
#define C_    50000
#define KSUB  3
#define NW    150000
#define SCALEF 64.0f
#define EPSN  1e-12f

// ---- GEMM tiling ----
#define BMg 128
#define BNg 96                   // 32 classes per tile
#define BKg 64                   // 64 fp16 = 128B rows in SMEM
#define NKC (D_/BKg)             // 8 chunks
#define NSTAGE_TOT NKC           // 8 stages
#define NRING 4
#define NTILE_N 1564             // ceil(150000/96)
#define NWP (NTILE_N*BNg)        // 150144 padded rows (zeros beyond NW)
#define NWARP 8                  // 256 threads: 4 warps/SMSP at 2 CTAs/SM

#define A_STG 16384              // 128 rows x 128B
#define B_STG 12288              // 96 rows x 128B
#define STG   (A_STG + B_STG)    // 28672
#define DYN_SMEM (NRING*STG)     // 114688 -> 2 CTAs/SM

// ---- static device scratch ----
__device__ float g_xn[B_*D_];                 // normalized x fp32 (fixup)
__device__ float g_winv[NW];                  // 1/||w|| (fixup)
__device__ __half g_xph[NKC*B_*64];           // packed swizzled x_hi [c][m][64]
__device__ __half g_wph[(size_t)NKC*NWP*64];  // packed swizzled w_hi [c][n][64]

// ============================ helpers ============================
__device__ __forceinline__ uint32_t smem_u32(const void* p) {
    uint32_t a;
    asm("{ .reg .u64 t; cvta.to.shared.u64 t, %1; cvt.u32.u64 %0, t; }" : "=r"(a) : "l"(p));
    return a;
}
__device__ __forceinline__ void ldsm_x4(uint32_t& r0, uint32_t& r1, uint32_t& r2,
                                        uint32_t& r3, uint32_t addr) {
    asm volatile("ldmatrix.sync.aligned.m8n8.x4.shared.b16 {%0,%1,%2,%3}, [%4];"
        : "=r"(r0), "=r"(r1), "=r"(r2), "=r"(r3) : "r"(addr));
}
__device__ __forceinline__ void mma16816(float* c, const uint32_t* a, const uint32_t* b) {
    asm volatile(
        "mma.sync.aligned.m16n8k16.row.col.f32.f16.f16.f32 "
        "{%0,%1,%2,%3}, {%4,%5,%6,%7}, {%8,%9}, {%0,%1,%2,%3};"
        : "+f"(c[0]), "+f"(c[1]), "+f"(c[2]), "+f"(c[3])
        : "r"(a[0]), "r"(a[1]), "r"(a[2]), "r"(a[3]), "r"(b[0]), "r"(b[1]));
}
__device__ __forceinline__ void bulk_g2s(uint32_t dst, const void* src,
                                         uint32_t bytes, uint32_t mbar) {
    asm volatile(
        "cp.async.bulk.shared::cta.global.mbarrier::complete_tx::bytes [%0], [%1], %2, [%3];"
        :: "r"(dst), "l"(src), "r"(bytes), "r"(mbar) : "memory");
}
#define MBAR_INIT(a, n) asm volatile("mbarrier.init.shared.b64 [%0], %1;" :: "r"(a), "r"(n) : "memory")
#define MBAR_ARRIVE(a)  asm volatile("mbarrier.arrive.shared.b64 _, [%0];" :: "r"(a) : "memory")
#define MBAR_EXPECT_TX(a, n) asm volatile("mbarrier.arrive.expect_tx.shared.b64 _, [%0], %1;" :: "r"(a), "r"(n) : "memory")
#define MBAR_WAIT(a, par) do {                                                     \
    asm volatile(                                                                  \
        "{\n\t.reg .pred P1;\n\t"                                                  \
        "WL_%=:\n\t"                                                               \
        "mbarrier.try_wait.parity.acquire.cta.shared::cta.b64 P1, [%0], %1, 0x989680;\n\t" \
        "@P1 bra.uni WD_%=;\n\t"                                                   \
        "bra.uni WL_%=;\n\t"                                                       \
        "WD_%=:\n\t}"                                                              \
        :: "r"(a), "r"(par) : "memory");                                           \
} while (0)

// packed element offset: chunk c, global row, within-chunk 16B sub ci, sub-off
__device__ __forceinline__ size_t pack_off(int c, size_t rowStride, int row, int ci, int off) {
    return ((size_t)c * rowStride + row) * 64 + (size_t)((ci ^ (row & 7)) << 3) + off;
}

// ============================ Kernel 0: x prep ============================
__global__ void xprep_kernel(const float* __restrict__ x) {
    __shared__ float red[4];
    const int m = blockIdx.x;
    const int tid = threadIdx.x;            // 0..127, covers k = 4*tid
    float4 v = reinterpret_cast<const float4*>(x + m * D_)[tid];
    float ss = v.x * v.x + v.y * v.y + v.z * v.z + v.w * v.w;
    #pragma unroll
    for (int o = 16; o > 0; o >>= 1) ss += __shfl_xor_sync(0xffffffffu, ss, o);
    if ((tid & 31) == 0) red[tid >> 5] = ss;
    __syncthreads();
    float inv = 1.0f / fmaxf(sqrtf(red[0] + red[1] + red[2] + red[3]), EPSN);
    float u[4] = {v.x * inv, v.y * inv, v.z * inv, v.w * inv};
    reinterpret_cast<float4*>(g_xn)[m * (D_ / 4) + tid] =
        make_float4(u[0], u[1], u[2], u[3]);
    __half h[4];
    #pragma unroll
    for (int i = 0; i < 4; i++) h[i] = __float2half_rn(u[i]);
    int c  = tid >> 4;
    int ci = (tid & 15) >> 1;
    int of = 4 * (tid & 1);
    size_t e = pack_off(c, B_, m, ci, of);
    *reinterpret_cast<uint2*>(g_xph + e) = *reinterpret_cast<uint2*>(h);
}

// ============================ Kernel 1: w prep ============================
__global__ void wprep_kernel(const float* __restrict__ w) {
    const int lane = threadIdx.x & 31;
    const int warp = threadIdx.x >> 5;
    const int n    = blockIdx.x * 8 + warp;   // NW divisible by 8
    const float4* wr = reinterpret_cast<const float4*>(w + (size_t)n * D_);
    float4 v[4];
    float ss = 0.0f;
    #pragma unroll
    for (int i = 0; i < 4; i++) {
        v[i] = wr[lane + i * 32];
        ss += v[i].x * v[i].x + v[i].y * v[i].y + v[i].z * v[i].z + v[i].w * v[i].w;
    }
    #pragma unroll
    for (int o = 16; o > 0; o >>= 1) ss += __shfl_xor_sync(0xffffffffu, ss, o);
    float inv = 1.0f / fmaxf(sqrtf(ss), EPSN);
    if (lane == 0) g_winv[n] = inv;
    #pragma unroll
    for (int i = 0; i < 4; i++) {
        __half h[4];
        h[0] = __float2half_rn(v[i].x * inv);
        h[1] = __float2half_rn(v[i].y * inv);
        h[2] = __float2half_rn(v[i].z * inv);
        h[3] = __float2half_rn(v[i].w * inv);
        int c  = (lane >> 4) + 2 * i;         // k = 4*lane + 128*i
        int ci = (lane & 15) >> 1;
        int of = 4 * (lane & 1);
        *reinterpret_cast<uint2*>(g_wph + pack_off(c, NWP, n, ci, of)) =
            *reinterpret_cast<uint2*>(h);
    }
}

// ============================ Kernel 2: HMMA GEMM + max-3 (8 warps) ====================
__global__ __launch_bounds__(256)
void gemm_hmma_kernel(float* __restrict__ out) {
    extern __shared__ __align__(1024) char dyn[];
    __shared__ __align__(8) uint64_t sFull[NRING], sEmpty[NRING];

    const uint32_t sb  = smem_u32(dyn);
    const int tid  = threadIdx.x;
    const int lane = tid & 31;
    const int wid  = tid >> 5;              // 0..7
    const int wm   = wid >> 1;              // 0..3 (32 rows each)
    const int wn   = wid & 1;               // 0..1 (48 cols each)
    const int mblk = blockIdx.x * BMg;      // M fastest -> stripe L2 reuse
    const int nb   = NTILE_N - 1 - blockIdx.y;  // reversed: hit wprep's L2 tail
    const int nblk = nb * BNg;

    if (tid == 0) {
        #pragma unroll
        for (int i = 0; i < NRING; i++) {
            MBAR_INIT(smem_u32(&sFull[i]), 1);
            MBAR_INIT(smem_u32(&sEmpty[i]), NWARP);
        }
    }
    __syncthreads();

    // producer: issue stage t (chunk t)
    auto produce = [&](int t) {
        int slot = t & (NRING - 1);
        if (t >= NRING) MBAR_WAIT(smem_u32(&sEmpty[slot]), 1 ^ ((t >> 2) & 1));
        uint32_t fb = smem_u32(&sFull[slot]);
        MBAR_EXPECT_TX(fb, STG);
        const __half* aSrc = g_xph + ((size_t)t * B_ + mblk) * 64;
        const __half* bSrc = g_wph + ((size_t)t * NWP + nblk) * 64;
        uint32_t base = sb + slot * STG;
        bulk_g2s(base, aSrc, A_STG, fb);
        bulk_g2s(base + A_STG, bSrc, B_STG, fb);
    };

    if (tid == 0) { produce(0); produce(1); produce(2); }

    float acc[2][6][4];
    #pragma unroll
    for (int i = 0; i < 2; i++)
        #pragma unroll
        for (int j = 0; j < 6; j++)
            #pragma unroll
            for (int q = 0; q < 4; q++) acc[i][j][q] = 0.0f;

    for (int s = 0; s < NSTAGE_TOT; s++) {
        int slot = s & (NRING - 1);
        MBAR_WAIT(smem_u32(&sFull[slot]), (s >> 2) & 1);
        uint32_t aBase = sb + slot * STG;
        uint32_t bBase = aBase + A_STG;

        #pragma unroll
        for (int kk = 0; kk < 4; kk++) {            // 4 k16 steps in BK=64
            const int ciA = 2 * kk + (lane >> 4);   // 16B chunk index
            uint32_t a[2][4];
            #pragma unroll
            for (int mt = 0; mt < 2; mt++) {
                int rr = wm * 32 + mt * 16 + (lane & 15);
                uint32_t ad = aBase + rr * 128 + (((ciA ^ (rr & 7))) << 4);
                ldsm_x4(a[mt][0], a[mt][1], a[mt][2], a[mt][3], ad);
            }
            uint32_t b[6][2];
            #pragma unroll
            for (int p = 0; p < 3; p++) {
                int rr = wn * 48 + p * 16 + (lane & 15);
                uint32_t ad = bBase + rr * 128 + (((ciA ^ (rr & 7))) << 4);
                uint32_t r0, r1, r2, r3;
                ldsm_x4(r0, r1, r2, r3, ad);
                b[2 * p][0] = r0; b[2 * p][1] = r2;
                b[2 * p + 1][0] = r1; b[2 * p + 1][1] = r3;
            }
            #pragma unroll
            for (int mt = 0; mt < 2; mt++)
                #pragma unroll
                for (int nt = 0; nt < 6; nt++)
                    mma16816(acc[mt][nt], a[mt], b[nt]);
        }
        if (lane == 0) MBAR_ARRIVE(smem_u32(&sEmpty[slot]));  // per-warp arrive
        if (tid == 0 && s + 3 < NSTAGE_TOT) produce(s + 3);
    }
    __syncthreads();   // all stages consumed; smem ring free for staging

    // ---- epilogue: stage fp32 accs, max over class triples, store ----
    float* st = reinterpret_cast<float*>(dyn);     // [128][98]
    const int STR = 98;
    #pragma unroll
    for (int mt = 0; mt < 2; mt++) {
        int r0 = wm * 32 + mt * 16 + (lane >> 2);
        #pragma unroll
        for (int nt = 0; nt < 6; nt++) {
            int cc = wn * 48 + nt * 8 + 2 * (lane & 3);
            *reinterpret_cast<float2*>(&st[r0 * STR + cc]) =
                make_float2(acc[mt][nt][0], acc[mt][nt][1]);
            *reinterpret_cast<float2*>(&st[(r0 + 8) * STR + cc]) =
                make_float2(acc[mt][nt][2], acc[mt][nt][3]);
        }
    }
    __syncthreads();

    const int clsBase = nb * (BNg / KSUB);
    for (int t = tid; t < BMg * (BNg / KSUB); t += 256) {
        int r = t >> 5, cc = t & 31;
        int cls = clsBase + cc;
        if (cls < C_) {
            const float* p = &st[r * STR + 3 * cc];
            float v = fmaxf(p[0], fmaxf(p[1], p[2]));
            out[(size_t)(mblk + r) * C_ + cls] = SCALEF * v;
        }
    }
}

// ============================ Kernel 3: label fix-up ============================
__global__ void fixup_kernel(const int* __restrict__ label,
                             const float* __restrict__ w,
                             const float* __restrict__ margins,
                             float* __restrict__ out) {
    __shared__ float sdot[KSUB];
    const int b = blockIdx.x;
    const int lane = threadIdx.x & 31;
    const int warp = threadIdx.x >> 5;
    int l = label[b];
    if (l < 0) l = 0;
    if (l >= C_) l = C_ - 1;
    const int row = l * KSUB + warp;
    const float4* xr = reinterpret_cast<const float4*>(g_xn + (size_t)b * D_);
    const float4* wr = reinterpret_cast<const float4*>(w + (size_t)row * D_);
    float dot = 0.0f;
    #pragma unroll
    for (int i = 0; i < 4; i++) {
        float4 xa = xr[lane + i * 32];
        float4 wa = wr[lane + i * 32];
        dot += xa.x * wa.x + xa.y * wa.y + xa.z * wa.z + xa.w * wa.w;
    }
    #pragma unroll
    for (int o = 16; o > 0; o >>= 1) dot += __shfl_xor_sync(0xffffffffu, dot, o);
    if (lane == 0) sdot[warp] = dot * g_winv[row];
    __syncthreads();
    if (threadIdx.x == 0) {
        float c0 = sdot[0], c1 = sdot[1], c2 = sdot[2];
        float target = fmaxf(c0, fmaxf(c1, c2));
        float shift = 0.5f * (fabsf(c0 - c1) + fabsf(c0 - c2));
        float mg = margins[l];
        out[(size_t)b * C_ + l] = SCALEF * (target - mg * (1.0f + shift));
    }
}

// ============================ launch ============================
extern "C" void kernel_launch(void* const* d_in, const int* in_sizes, int n_in,
                              void* d_out, int out_size) {
    const float* input   = (const float*)d_in[0];      // (512, 512)
    const int*   label   = (const int*)d_in[1];        // (512,) int32
    const float* weights = (const float*)d_in[2];      // (150000, 512)
    const float* margins = (const float*)d_in[3];      // (50000,)
    float* out = (float*)d_out;                        // (512, 50000)

    cudaFuncSetAttribute(gemm_hmma_kernel,
                         cudaFuncAttributeMaxDynamicSharedMemorySize, DYN_SMEM);
    cudaFuncSetAttribute(gemm_hmma_kernel,
                         cudaFuncAttributePreferredSharedMemoryCarveout, 100);

    xprep_kernel<<<B_, 128>>>(input);
    wprep_kernel<<<NW / 8, 256>>>(weights);
    dim3 grid(B_ / BMg, NTILE_N);   // (4, 1564): M fastest; y reversed in-kernel
    gemm_hmma_kernel<<<grid, 256, DYN_SMEM>>>(out);
    fixup_kernel<<<B_, 96>>>(label, weights, margins, out);
}